// round 5
// baseline (speedup 1.0000x reference)
#include <cuda_runtime.h>
#include <math.h>

#define N_NODES 8192
#define E_MAX   262144
#define EDGES_TOTAL (2 * E_MAX)

// ---------------------------------------------------------------------------
// Device scratch (no cudaMalloc allowed)
// ---------------------------------------------------------------------------
__device__ float g_rowinv[N_NODES];          // row sums, then inverses
__device__ int   g_cnt[N_NODES];             // per-row edge counts
__device__ int   g_off[N_NODES + 1];         // CSR offsets
__device__ int   g_cur[N_NODES];             // running fill cursors
__device__ int   g_col[EDGES_TOTAL];         // CSR columns
__device__ float g_val[EDGES_TOTAL];         // CSR pre-normalized values

// ---------------------------------------------------------------------------
// Kernel 1: zero counters + row sums
// ---------------------------------------------------------------------------
__global__ void k_init() {
    int i = blockIdx.x * blockDim.x + threadIdx.x;
    if (i < N_NODES) {
        g_rowinv[i] = 0.0f;
        g_cnt[i] = 0;
    }
}

// ---------------------------------------------------------------------------
// Kernel 2: per-row counts + weighted row sums from both edge lists
// ---------------------------------------------------------------------------
__global__ void k_count_sum(const int* __restrict__ rows_s,
                            const float* __restrict__ vals_s,
                            const int* __restrict__ rows_t,
                            const float* __restrict__ vals_t,
                            const float* __restrict__ gamma,
                            int E) {
    int i = blockIdx.x * blockDim.x + threadIdx.x;
    float alpha = 1.0f / (1.0f + expf(-gamma[0]));
    int r; float v;
    if (i < E) {
        r = rows_s[i];
        v = alpha * vals_s[i];
    } else if (i < 2 * E) {
        int j = i - E;
        r = rows_t[j];
        v = (1.0f - alpha) * vals_t[j];
    } else {
        return;
    }
    atomicAdd(&g_cnt[r], 1);
    atomicAdd(&g_rowinv[r], v);
}

// ---------------------------------------------------------------------------
// Kernel 3: single-block prefix scan of counts -> offsets/cursors,
//           plus row-sum inversion. 1024 threads x 8 elements each.
// ---------------------------------------------------------------------------
__global__ void k_scan() {
    __shared__ int ssum[1024];
    int t = threadIdx.x;
    int base = t * 8;

    int local[8];
    int s = 0;
#pragma unroll
    for (int k = 0; k < 8; k++) {
        local[k] = g_cnt[base + k];
        s += local[k];
    }
    ssum[t] = s;
    __syncthreads();

    // Hillis-Steele inclusive scan over 1024 partial sums
    for (int off = 1; off < 1024; off <<= 1) {
        int v = (t >= off) ? ssum[t - off] : 0;
        __syncthreads();
        ssum[t] += v;
        __syncthreads();
    }

    int excl = ssum[t] - s;  // exclusive prefix for this thread's chunk
#pragma unroll
    for (int k = 0; k < 8; k++) {
        g_off[base + k] = excl;
        g_cur[base + k] = excl;
        excl += local[k];
        // invert row sums in the same pass
        float rv = g_rowinv[base + k];
        g_rowinv[base + k] = (rv == 0.0f) ? 1.0f : (1.0f / rv);
    }
    if (t == 1023) g_off[N_NODES] = ssum[1023];
}

// ---------------------------------------------------------------------------
// Kernel 4: fill CSR with (col, alpha_w * val * row_inv)
// ---------------------------------------------------------------------------
__global__ void k_fill(const int* __restrict__ rows_s,
                       const int* __restrict__ cols_s,
                       const float* __restrict__ vals_s,
                       const int* __restrict__ rows_t,
                       const int* __restrict__ cols_t,
                       const float* __restrict__ vals_t,
                       const float* __restrict__ gamma,
                       int E) {
    int i = blockIdx.x * blockDim.x + threadIdx.x;
    float alpha = 1.0f / (1.0f + expf(-gamma[0]));
    int r, c; float v;
    if (i < E) {
        r = rows_s[i];
        c = cols_s[i];
        v = alpha * vals_s[i];
    } else if (i < 2 * E) {
        int j = i - E;
        r = rows_t[j];
        c = cols_t[j];
        v = (1.0f - alpha) * vals_t[j];
    } else {
        return;
    }
    v *= g_rowinv[r];
    int pos = atomicAdd(&g_cur[r], 1);
    g_col[pos] = c;
    g_val[pos] = v;
}

// ---------------------------------------------------------------------------
// Kernel 5: one CTA per row — zero smem row, accumulate edges, stream out.
// This is the single 256MB store pass (replaces zero-fill + global scatter).
// ---------------------------------------------------------------------------
__global__ void __launch_bounds__(256) k_write(float* __restrict__ out) {
    __shared__ float row[N_NODES];  // 32 KB
    int r = blockIdx.x;
    int t = threadIdx.x;

    float4* row4 = (float4*)row;
#pragma unroll
    for (int k = 0; k < N_NODES / 4 / 256; k++)
        row4[t + k * 256] = make_float4(0.f, 0.f, 0.f, 0.f);
    __syncthreads();

    int s = g_off[r];
    int e = g_off[r + 1];
    for (int k = s + t; k < e; k += 256)
        atomicAdd(&row[g_col[k]], g_val[k]);
    __syncthreads();

    float4* o4 = (float4*)(out + (size_t)r * N_NODES);
#pragma unroll
    for (int k = 0; k < N_NODES / 4 / 256; k++) {
        // streaming store hint: write-once data, keep it out of L2's way
        __stcs(&o4[t + k * 256], row4[t + k * 256]);
    }
}

// ---------------------------------------------------------------------------
// Launcher
// ---------------------------------------------------------------------------
extern "C" void kernel_launch(void* const* d_in, const int* in_sizes, int n_in,
                              void* d_out, int out_size) {
    const int*   rows_s = (const int*)d_in[0];
    const int*   cols_s = (const int*)d_in[1];
    const float* vals_s = (const float*)d_in[2];
    const int*   rows_t = (const int*)d_in[3];
    const int*   cols_t = (const int*)d_in[4];
    const float* vals_t = (const float*)d_in[5];
    const float* gamma  = (const float*)d_in[6];
    float* out = (float*)d_out;

    const int E = in_sizes[0];
    const int total = 2 * E;

    k_init<<<(N_NODES + 255) / 256, 256>>>();
    k_count_sum<<<(total + 255) / 256, 256>>>(rows_s, vals_s, rows_t, vals_t,
                                              gamma, E);
    k_scan<<<1, 1024>>>();
    k_fill<<<(total + 255) / 256, 256>>>(rows_s, cols_s, vals_s,
                                         rows_t, cols_t, vals_t, gamma, E);
    k_write<<<N_NODES, 256>>>(out);
}

// round 9
// speedup vs baseline: 1.3343x; 1.3343x over previous
#include <cuda_runtime.h>
#include <math.h>

#define N_NODES 8192

// Row-sum scratch (no cudaMalloc allowed). Zeroed via cudaMemsetAsync.
__device__ float g_rowsum[N_NODES];

// ---------------------------------------------------------------------------
// Kernel 1: accumulate weighted per-row sums from both edge lists.
// atomicAdd result unused -> RED.ADD (fire-and-forget).
// ---------------------------------------------------------------------------
__global__ void k_rowsum(const int* __restrict__ rows_s,
                         const float* __restrict__ vals_s,
                         const int* __restrict__ rows_t,
                         const float* __restrict__ vals_t,
                         const float* __restrict__ gamma,
                         int E) {
    int i = blockIdx.x * blockDim.x + threadIdx.x;
    float alpha = 1.0f / (1.0f + __expf(-gamma[0]));
    if (i < E) {
        atomicAdd(&g_rowsum[rows_s[i]], alpha * vals_s[i]);
    } else if (i < 2 * E) {
        int j = i - E;
        atomicAdd(&g_rowsum[rows_t[j]], (1.0f - alpha) * vals_t[j]);
    }
}

// ---------------------------------------------------------------------------
// Kernel 2: scatter normalized values into the (pre-zeroed) dense output.
// Row sums are read hot out of L1/L2 (32KB table); divide on the fly.
// atomicAdd result unused -> RED.ADD.
// ---------------------------------------------------------------------------
__global__ void k_scatter(const int* __restrict__ rows_s,
                          const int* __restrict__ cols_s,
                          const float* __restrict__ vals_s,
                          const int* __restrict__ rows_t,
                          const int* __restrict__ cols_t,
                          const float* __restrict__ vals_t,
                          const float* __restrict__ gamma,
                          float* __restrict__ out,
                          int E) {
    int i = blockIdx.x * blockDim.x + threadIdx.x;
    float alpha = 1.0f / (1.0f + __expf(-gamma[0]));
    int r, c; float v;
    if (i < E) {
        r = rows_s[i];
        c = cols_s[i];
        v = alpha * vals_s[i];
    } else if (i < 2 * E) {
        int j = i - E;
        r = rows_t[j];
        c = cols_t[j];
        v = (1.0f - alpha) * vals_t[j];
    } else {
        return;
    }
    float rs = g_rowsum[r];
    rs = (rs == 0.0f) ? 1.0f : rs;
    atomicAdd(&out[(long long)r * N_NODES + c], __fdividef(v, rs));
}

// ---------------------------------------------------------------------------
// Launcher: memset(rowsum) -> rowsum -> memset(out, 256MB) -> scatter
// ---------------------------------------------------------------------------
extern "C" void kernel_launch(void* const* d_in, const int* in_sizes, int n_in,
                              void* d_out, int out_size) {
    const int*   rows_s = (const int*)d_in[0];
    const int*   cols_s = (const int*)d_in[1];
    const float* vals_s = (const float*)d_in[2];
    const int*   rows_t = (const int*)d_in[3];
    const int*   cols_t = (const int*)d_in[4];
    const float* vals_t = (const float*)d_in[5];
    const float* gamma  = (const float*)d_in[6];
    float* out = (float*)d_out;

    const int E = in_sizes[0];
    const int total = 2 * E;

    void* rowsum_ptr = nullptr;
    cudaGetSymbolAddress(&rowsum_ptr, g_rowsum);

    // Zero the 32KB row-sum scratch (0x00 bytes == 0.0f).
    cudaMemsetAsync(rowsum_ptr, 0, N_NODES * sizeof(float));

    // Per-row weighted sums.
    k_rowsum<<<(total + 255) / 256, 256>>>(rows_s, vals_s, rows_t, vals_t,
                                           gamma, E);

    // Zero the 256MB dense output via the driver's tuned memset path.
    cudaMemsetAsync(out, 0, (size_t)out_size * sizeof(float));

    // Scatter normalized values.
    k_scatter<<<(total + 255) / 256, 256>>>(rows_s, cols_s, vals_s,
                                            rows_t, cols_t, vals_t,
                                            gamma, out, E);
}

// round 11
// speedup vs baseline: 1.5518x; 1.1630x over previous
#include <cuda_runtime.h>
#include <math.h>

#define N_NODES 8192

// Row-sum scratch (no cudaMalloc allowed). Zeroed via cudaMemsetAsync.
__device__ float g_rowsum[N_NODES];

// ---------------------------------------------------------------------------
// Fused kernel: blocks [0, edge_blocks) accumulate weighted per-row sums
// (RED.ADD into the 32KB L2-resident table); blocks [edge_blocks, ...) stream
// zeros into the 256MB output. The two halves are independent, so the rowsum
// phase hides entirely inside the compulsory zero-fill pass.
//
// Zero layout: each zero block writes 2048 consecutive float4 (32KB) with
// 8 x 256 coalesced __stcs stores.
// ---------------------------------------------------------------------------
__global__ void __launch_bounds__(256)
k_zero_rowsum(const int* __restrict__ rows_s,
              const float* __restrict__ vals_s,
              const int* __restrict__ rows_t,
              const float* __restrict__ vals_t,
              const float* __restrict__ gamma,
              float4* __restrict__ out4,
              long long n4,
              int E, int edge_blocks) {
    int b = blockIdx.x;
    int t = threadIdx.x;

    if (b < edge_blocks) {
        int i = b * 256 + t;
        float alpha = 1.0f / (1.0f + __expf(-gamma[0]));
        if (i < E) {
            atomicAdd(&g_rowsum[rows_s[i]], alpha * vals_s[i]);
        } else if (i < 2 * E) {
            int j = i - E;
            atomicAdd(&g_rowsum[rows_t[j]], (1.0f - alpha) * vals_t[j]);
        }
        return;
    }

    long long base = (long long)(b - edge_blocks) * 2048 + t;
    const float4 z = make_float4(0.f, 0.f, 0.f, 0.f);
#pragma unroll
    for (int k = 0; k < 8; k++) {
        long long idx = base + (long long)k * 256;
        if (idx < n4) __stcs(&out4[idx], z);
    }
}

// ---------------------------------------------------------------------------
// Scatter kernel: normalized values into the (pre-zeroed) dense output.
// Row sums read hot from L1/L2 (32KB table); atomicAdd result unused -> RED.
// ---------------------------------------------------------------------------
__global__ void __launch_bounds__(256)
k_scatter(const int* __restrict__ rows_s,
          const int* __restrict__ cols_s,
          const float* __restrict__ vals_s,
          const int* __restrict__ rows_t,
          const int* __restrict__ cols_t,
          const float* __restrict__ vals_t,
          const float* __restrict__ gamma,
          float* __restrict__ out,
          int E) {
    int i = blockIdx.x * blockDim.x + threadIdx.x;
    float alpha = 1.0f / (1.0f + __expf(-gamma[0]));
    int r, c; float v;
    if (i < E) {
        r = rows_s[i];
        c = cols_s[i];
        v = alpha * vals_s[i];
    } else if (i < 2 * E) {
        int j = i - E;
        r = rows_t[j];
        c = cols_t[j];
        v = (1.0f - alpha) * vals_t[j];
    } else {
        return;
    }
    float rs = g_rowsum[r];
    rs = (rs == 0.0f) ? 1.0f : rs;
    atomicAdd(&out[(long long)r * N_NODES + c], __fdividef(v, rs));
}

// ---------------------------------------------------------------------------
// Launcher: memset(rowsum 32KB) -> fused(zero 256MB || rowsum) -> scatter
// ---------------------------------------------------------------------------
extern "C" void kernel_launch(void* const* d_in, const int* in_sizes, int n_in,
                              void* d_out, int out_size) {
    const int*   rows_s = (const int*)d_in[0];
    const int*   cols_s = (const int*)d_in[1];
    const float* vals_s = (const float*)d_in[2];
    const int*   rows_t = (const int*)d_in[3];
    const int*   cols_t = (const int*)d_in[4];
    const float* vals_t = (const float*)d_in[5];
    const float* gamma  = (const float*)d_in[6];
    float* out = (float*)d_out;

    const int E = in_sizes[0];
    const int total = 2 * E;

    void* rowsum_ptr = nullptr;
    cudaGetSymbolAddress(&rowsum_ptr, g_rowsum);
    cudaMemsetAsync(rowsum_ptr, 0, N_NODES * sizeof(float));

    // Fused zero-fill + rowsum
    long long n4 = (long long)out_size / 4;                // float4 count
    int edge_blocks = (total + 255) / 256;                 // 2048
    int zero_blocks = (int)((n4 + 2047) / 2048);           // 8192
    k_zero_rowsum<<<edge_blocks + zero_blocks, 256>>>(
        rows_s, vals_s, rows_t, vals_t, gamma,
        (float4*)out, n4, E, edge_blocks);

    // Scatter normalized values.
    k_scatter<<<(total + 255) / 256, 256>>>(rows_s, cols_s, vals_s,
                                            rows_t, cols_t, vals_t,
                                            gamma, out, E);
}